// round 17
// baseline (speedup 1.0000x reference)
#include <cuda_runtime.h>
#include <cuda_bf16.h>
#include <cuda_fp16.h>
#include <float.h>

// Problem constants (fixed by the dataset)
#define NMAX 50000
#define EMAX 800000
#define HD   128   // H*D
#define H8   8

// ---------------- scratch (device globals; no allocation allowed) ----------
__device__ float g_hf   [NMAX * HD];   // nfeat @ W_fc (fp32, for GEMM1 epilogue)
__device__ uint2 g_hf16 [NMAX * 32];   // fp16 shadow of hf (4 halves per uint2)
__device__ float g_S    [NMAX * HD];   // normalized attention aggregate
__device__ float g_Esum [NMAX * HD];   // segment_sum(efeat, dst)
__device__ float g_el   [NMAX * H8];
__device__ float g_er   [NMAX * H8];
__device__ float g_indeg[NMAX];
// CSR build
__device__ int  g_cnt [NMAX];
__device__ int  g_off [NMAX + 1];
__device__ int  g_pos [NMAX];
__device__ int  g_bsum[64];
__device__ int2 g_edge[EMAX];          // (eid, src) grouped by dst

// ---------------- helpers ----------------------------------------------------
__device__ __forceinline__ void bf16_split(float x, unsigned short& hi,
                                           unsigned short& lo) {
    __nv_bfloat16 h = __float2bfloat16(x);
    hi = __bfloat16_as_ushort(h);
    lo = __bfloat16_as_ushort(__float2bfloat16(x - __bfloat162float(h)));
}

__device__ __forceinline__ void mma_bf16(float* c, unsigned a0, unsigned a1,
                                         unsigned a2, unsigned a3,
                                         unsigned b0, unsigned b1) {
    asm volatile(
        "mma.sync.aligned.m16n8k16.row.col.f32.bf16.bf16.f32 "
        "{%0,%1,%2,%3}, {%4,%5,%6,%7}, {%8,%9}, {%0,%1,%2,%3};"
        : "+f"(c[0]), "+f"(c[1]), "+f"(c[2]), "+f"(c[3])
        : "r"(a0), "r"(a1), "r"(a2), "r"(a3), "r"(b0), "r"(b1));
}

// ---------------- CSR build kernels -----------------------------------------
__global__ void zero_cnt_kernel(int N) {
    int i = blockIdx.x * blockDim.x + threadIdx.x;
    if (i < N) g_cnt[i] = 0;
}

__global__ void hist_kernel(const int* __restrict__ dst, int E) {
    int e = blockIdx.x * blockDim.x + threadIdx.x;
    if (e < E) atomicAdd(&g_cnt[dst[e]], 1);
}

__global__ void __launch_bounds__(1024) scan1_kernel(int N) {
    __shared__ int sm[1024];
    int i = blockIdx.x * 1024 + threadIdx.x;
    int v = (i < N) ? g_cnt[i] : 0;
    sm[threadIdx.x] = v;
    __syncthreads();
    #pragma unroll
    for (int off = 1; off < 1024; off <<= 1) {
        int t = (threadIdx.x >= off) ? sm[threadIdx.x - off] : 0;
        __syncthreads();
        sm[threadIdx.x] += t;
        __syncthreads();
    }
    if (i < N) g_off[i] = sm[threadIdx.x] - v;
    if (threadIdx.x == 1023) g_bsum[blockIdx.x] = sm[1023];
}

__global__ void scan3_kernel(int nb, int E, int N) {
    __shared__ int sincl[64];
    __shared__ int sexcl[64];
    int tid = threadIdx.x;
    int v = 0;
    if (tid < 64) {
        v = (tid < nb) ? g_bsum[tid] : 0;
        sincl[tid] = v;
    }
    __syncthreads();
    #pragma unroll
    for (int off = 1; off < 64; off <<= 1) {
        int t = (tid >= off && tid < 64) ? sincl[tid - off] : 0;
        __syncthreads();
        if (tid < 64) sincl[tid] += t;
        __syncthreads();
    }
    if (tid < 64) sexcl[tid] = sincl[tid] - v;
    __syncthreads();
    int i = blockIdx.x * blockDim.x + tid;
    if (i < N) {
        int o = g_off[i] + sexcl[i >> 10];
        g_off[i] = o;
        g_pos[i] = o;
    }
    if (blockIdx.x == 0 && tid == 0) g_off[N] = E;
}

__global__ void scatter_eid_kernel(const int* __restrict__ src,
                                   const int* __restrict__ dst, int E) {
    int e = blockIdx.x * blockDim.x + threadIdx.x;
    if (e >= E) return;
    int d = dst[e];
    int p = atomicAdd(&g_pos[d], 1);
    g_edge[p] = make_int2(e, src[e]);
}

// ---------------- tensor-core GEMM: 64 rows/CTA, 128 cols, K=128 ------------
// Split-bf16 3-product (AhiBhi + AhiBlo + AloBhi) via mma.sync m16n8k16.
// smem (padded rows of 136 bf16 for conflict-free frag loads):
//   Xhi[64][136], Xlo[64][136], WThi[128][136], WTlo[128][136]
#define RPAD 136
#define SM_XHI  0
#define SM_XLO  (64 * RPAD * 2)
#define SM_WTHI (2 * 64 * RPAD * 2)
#define SM_WTLO (SM_WTHI + 128 * RPAD * 2)
#define SM_TOTAL (SM_WTLO + 128 * RPAD * 2)   // 104448 B

// MODE 0: hf = nfeat @ W_fc ; epilogue: hf, fp16 shadow, el/er
// MODE 1: tmp = Esum @ W_e  ; epilogue: final combine into out
template <int MODE>
__global__ void __launch_bounds__(256) gemm128_kernel(
    const float* __restrict__ Xin, const float* __restrict__ W, int nrows,
    const float* __restrict__ attn_l, const float* __restrict__ attn_r,
    const float* __restrict__ bias,  const float* __restrict__ b_e,
    float* __restrict__ out)
{
    extern __shared__ char smem[];
    __shared__ float attnsm[256];

    const float* X = (MODE == 0) ? Xin : (const float*)g_Esum;

    int tid  = threadIdx.x;
    int lane = tid & 31;
    int warp = tid >> 5;
    int rowbase = blockIdx.x * 64;

    // ---- W^T fill: W[k][n] (n contiguous) -> WT[n][k], split bf16 ----
    {
        const float4* W4 = (const float4*)W;
        for (int i = tid; i < 4096; i += 256) {
            int k  = i >> 5;
            int n4 = (i & 31) * 4;
            float4 v = W4[k * 32 + (n4 >> 2)];
            float vv[4] = {v.x, v.y, v.z, v.w};
            #pragma unroll
            for (int j = 0; j < 4; j++) {
                unsigned short h, l;
                bf16_split(vv[j], h, l);
                int off = ((n4 + j) * RPAD + k) * 2;
                *(unsigned short*)(smem + SM_WTHI + off) = h;
                *(unsigned short*)(smem + SM_WTLO + off) = l;
            }
        }
    }

    // ---- X fill: rows rowbase..+63, split bf16, packed uint stores ----
    {
        const float4* X4 = (const float4*)X;
        for (int i = tid; i < 2048; i += 256) {
            int r  = i >> 5;
            int c4 = (i & 31) * 4;
            int gr = rowbase + r;
            float4 v = (gr < nrows) ? __ldg(&X4[(size_t)gr * 32 + (c4 >> 2)])
                                    : make_float4(0.f, 0.f, 0.f, 0.f);
            unsigned short h0, h1, h2, h3, l0, l1, l2, l3;
            bf16_split(v.x, h0, l0); bf16_split(v.y, h1, l1);
            bf16_split(v.z, h2, l2); bf16_split(v.w, h3, l3);
            int off = (r * RPAD + c4) * 2;
            *(unsigned int*)(smem + SM_XHI + off)     = (unsigned)h0 | ((unsigned)h1 << 16);
            *(unsigned int*)(smem + SM_XHI + off + 4) = (unsigned)h2 | ((unsigned)h3 << 16);
            *(unsigned int*)(smem + SM_XLO + off)     = (unsigned)l0 | ((unsigned)l1 << 16);
            *(unsigned int*)(smem + SM_XLO + off + 4) = (unsigned)l2 | ((unsigned)l3 << 16);
        }
    }

    if (MODE == 0 && tid < 128) {
        attnsm[tid]       = attn_l[tid];
        attnsm[128 + tid] = attn_r[tid];
    }
    __syncthreads();

    int g = lane >> 2;          // groupID (0..7)
    int t = lane & 3;           // thread-in-group
    int mrow0 = (warp & 3) * 16;
    int ncol0 = (warp >> 2) * 64;

    float c[8][4];
    #pragma unroll
    for (int nt = 0; nt < 8; nt++)
        { c[nt][0] = 0.f; c[nt][1] = 0.f; c[nt][2] = 0.f; c[nt][3] = 0.f; }

    const char* XH = smem + SM_XHI;
    const char* XL = smem + SM_XLO;
    const char* WH = smem + SM_WTHI;
    const char* WL = smem + SM_WTLO;

    #pragma unroll
    for (int ks = 0; ks < 8; ks++) {
        int kb = ks * 16;
        int ea = ((mrow0 + g) * RPAD + kb + 2 * t) * 2;       // row g
        int eb = ea + 8 * RPAD * 2;                           // row g+8
        unsigned ah0 = *(const unsigned*)(XH + ea);
        unsigned ah1 = *(const unsigned*)(XH + eb);
        unsigned ah2 = *(const unsigned*)(XH + ea + 16);      // +8 cols
        unsigned ah3 = *(const unsigned*)(XH + eb + 16);
        unsigned al0 = *(const unsigned*)(XL + ea);
        unsigned al1 = *(const unsigned*)(XL + eb);
        unsigned al2 = *(const unsigned*)(XL + ea + 16);
        unsigned al3 = *(const unsigned*)(XL + eb + 16);
        #pragma unroll
        for (int nt = 0; nt < 8; nt++) {
            int wb = ((ncol0 + nt * 8 + g) * RPAD + kb + 2 * t) * 2;
            unsigned bh0 = *(const unsigned*)(WH + wb);
            unsigned bh1 = *(const unsigned*)(WH + wb + 16);  // k+8
            unsigned bl0 = *(const unsigned*)(WL + wb);
            unsigned bl1 = *(const unsigned*)(WL + wb + 16);
            mma_bf16(c[nt], ah0, ah1, ah2, ah3, bh0, bh1);
            mma_bf16(c[nt], ah0, ah1, ah2, ah3, bl0, bl1);
            mma_bf16(c[nt], al0, al1, al2, al3, bh0, bh1);
        }
    }

    // C layout: c0=(row g, col 2t), c1=(g, 2t+1), c2=(g+8, 2t), c3=(g+8, 2t+1)
    int gr0 = rowbase + mrow0 + g;
    int gr1 = gr0 + 8;
    bool v0 = (gr0 < nrows);
    bool v1 = (gr1 < nrows);

    if (MODE == 0) {
        float el0[4], er0[4], el1[4], er1[4];
        #pragma unroll
        for (int lh = 0; lh < 4; lh++)
            { el0[lh] = 0.f; er0[lh] = 0.f; el1[lh] = 0.f; er1[lh] = 0.f; }
        unsigned int* hf16w = (unsigned int*)g_hf16;
        #pragma unroll
        for (int nt = 0; nt < 8; nt++) {
            int col = ncol0 + nt * 8 + 2 * t;
            if (v0) {
                *(float2*)(g_hf + (size_t)gr0 * HD + col) = make_float2(c[nt][0], c[nt][1]);
                __half2 hp = __floats2half2_rn(c[nt][0], c[nt][1]);
                hf16w[gr0 * 64 + (col >> 1)] = *(unsigned int*)&hp;
            }
            if (v1) {
                *(float2*)(g_hf + (size_t)gr1 * HD + col) = make_float2(c[nt][2], c[nt][3]);
                __half2 hp = __floats2half2_rn(c[nt][2], c[nt][3]);
                hf16w[gr1 * 64 + (col >> 1)] = *(unsigned int*)&hp;
            }
            int lh = nt >> 1;
            float al0v = attnsm[col],       al1v = attnsm[col + 1];
            float ar0v = attnsm[128 + col], ar1v = attnsm[128 + col + 1];
            el0[lh] += c[nt][0] * al0v + c[nt][1] * al1v;
            er0[lh] += c[nt][0] * ar0v + c[nt][1] * ar1v;
            el1[lh] += c[nt][2] * al0v + c[nt][3] * al1v;
            er1[lh] += c[nt][2] * ar0v + c[nt][3] * ar1v;
        }
        #pragma unroll
        for (int lh = 0; lh < 4; lh++) {
            el0[lh] += __shfl_xor_sync(0xffffffffu, el0[lh], 1);
            el0[lh] += __shfl_xor_sync(0xffffffffu, el0[lh], 2);
            er0[lh] += __shfl_xor_sync(0xffffffffu, er0[lh], 1);
            er0[lh] += __shfl_xor_sync(0xffffffffu, er0[lh], 2);
            el1[lh] += __shfl_xor_sync(0xffffffffu, el1[lh], 1);
            el1[lh] += __shfl_xor_sync(0xffffffffu, el1[lh], 2);
            er1[lh] += __shfl_xor_sync(0xffffffffu, er1[lh], 1);
            er1[lh] += __shfl_xor_sync(0xffffffffu, er1[lh], 2);
        }
        if (t == 0) {
            int hbase = ncol0 >> 4;
            #pragma unroll
            for (int lh = 0; lh < 4; lh++) {
                if (v0) {
                    g_el[gr0 * H8 + hbase + lh] = el0[lh];
                    g_er[gr0 * H8 + hbase + lh] = er0[lh];
                }
                if (v1) {
                    g_el[gr1 * H8 + hbase + lh] = el1[lh];
                    g_er[gr1 * H8 + hbase + lh] = er1[lh];
                }
            }
        }
    } else {
        float indeg0 = v0 ? g_indeg[gr0] : 0.f;
        float indeg1 = v1 ? g_indeg[gr1] : 0.f;
        float rs0  = 1.f / (indeg0 + 1.f), rme0 = 1.f / fmaxf(indeg0, 1.f);
        float rs1  = 1.f / (indeg1 + 1.f), rme1 = 1.f / fmaxf(indeg1, 1.f);
        #pragma unroll
        for (int nt = 0; nt < 8; nt++) {
            int col = ncol0 + nt * 8 + 2 * t;
            float2 b2  = *(const float2*)(bias + col);
            float2 be2 = *(const float2*)(b_e  + col);
            if (v0) {
                float2 S2  = *(const float2*)(g_S  + (size_t)gr0 * HD + col);
                float2 hf2 = *(const float2*)(g_hf + (size_t)gr0 * HD + col);
                float2 o;
                o.x = S2.x + b2.x + hf2.x * rs0 + (c[nt][0] + indeg0 * be2.x) * rme0;
                o.y = S2.y + b2.y + hf2.y * rs0 + (c[nt][1] + indeg0 * be2.y) * rme0;
                *(float2*)(out + (size_t)gr0 * HD + col) = o;
            }
            if (v1) {
                float2 S2  = *(const float2*)(g_S  + (size_t)gr1 * HD + col);
                float2 hf2 = *(const float2*)(g_hf + (size_t)gr1 * HD + col);
                float2 o;
                o.x = S2.x + b2.x + hf2.x * rs1 + (c[nt][2] + indeg1 * be2.x) * rme1;
                o.y = S2.y + b2.y + hf2.y * rs1 + (c[nt][3] + indeg1 * be2.y) * rme1;
                *(float2*)(out + (size_t)gr1 * HD + col) = o;
            }
        }
    }
}

// ---------------- fused per-node gather (softmax + aggregate + Esum) --------
// One warp per dst node, edges grouped by dst via CSR.
// Softmax without max subtraction (shift-invariant; scores are O(1) here).
// hf read as fp16 shadow (halves LTS traffic); scores/denom/efeat stay fp32.
__global__ void __launch_bounds__(256) gather_kernel(
    const float* __restrict__ efeat, int N)
{
    int gtid = blockIdx.x * blockDim.x + threadIdx.x;
    int n    = gtid >> 5;
    int lane = gtid & 31;
    if (n >= N) return;

    int beg = g_off[n];
    int end = g_off[n + 1];

    float er_l = 0.f;
    if (lane < 8) er_l = g_er[n * H8 + lane];

    float  denom = 0.f;
    float4 accS  = make_float4(0.f, 0.f, 0.f, 0.f);
    float4 accE  = make_float4(0.f, 0.f, 0.f, 0.f);

    const float4* ef4 = (const float4*)efeat;

    int j = beg;
    for (; j + 3 < end; j += 4) {
        int2 a = g_edge[j];
        int2 b = g_edge[j + 1];
        int2 c = g_edge[j + 2];
        int2 d = g_edge[j + 3];
        uint2  hv0 = __ldg(&g_hf16[(size_t)a.y * 32 + lane]);
        uint2  hv1 = __ldg(&g_hf16[(size_t)b.y * 32 + lane]);
        uint2  hv2 = __ldg(&g_hf16[(size_t)c.y * 32 + lane]);
        uint2  hv3 = __ldg(&g_hf16[(size_t)d.y * 32 + lane]);
        float4 ev0 = __ldg(&ef4[(size_t)a.x * 32 + lane]);
        float4 ev1 = __ldg(&ef4[(size_t)b.x * 32 + lane]);
        float4 ev2 = __ldg(&ef4[(size_t)c.x * 32 + lane]);
        float4 ev3 = __ldg(&ef4[(size_t)d.x * 32 + lane]);
        float ex0 = 0.f, ex1 = 0.f, ex2 = 0.f, ex3 = 0.f;
        if (lane < 8) {
            float s0 = g_el[a.y * H8 + lane] + er_l;
            float s1 = g_el[b.y * H8 + lane] + er_l;
            float s2 = g_el[c.y * H8 + lane] + er_l;
            float s3 = g_el[d.y * H8 + lane] + er_l;
            s0 = s0 >= 0.f ? s0 : 0.2f * s0;
            s1 = s1 >= 0.f ? s1 : 0.2f * s1;
            s2 = s2 >= 0.f ? s2 : 0.2f * s2;
            s3 = s3 >= 0.f ? s3 : 0.2f * s3;
            ex0 = __expf(s0);
            ex1 = __expf(s1);
            ex2 = __expf(s2);
            ex3 = __expf(s3);
            denom += (ex0 + ex1) + (ex2 + ex3);
        }
        float e0 = __shfl_sync(0xffffffffu, ex0, lane >> 2);
        float e1 = __shfl_sync(0xffffffffu, ex1, lane >> 2);
        float e2 = __shfl_sync(0xffffffffu, ex2, lane >> 2);
        float e3 = __shfl_sync(0xffffffffu, ex3, lane >> 2);
        float2 f0a = __half22float2(*(__half2*)&hv0.x);
        float2 f0b = __half22float2(*(__half2*)&hv0.y);
        float2 f1a = __half22float2(*(__half2*)&hv1.x);
        float2 f1b = __half22float2(*(__half2*)&hv1.y);
        float2 f2a = __half22float2(*(__half2*)&hv2.x);
        float2 f2b = __half22float2(*(__half2*)&hv2.y);
        float2 f3a = __half22float2(*(__half2*)&hv3.x);
        float2 f3b = __half22float2(*(__half2*)&hv3.y);
        accS.x += e0 * f0a.x + e1 * f1a.x + e2 * f2a.x + e3 * f3a.x;
        accS.y += e0 * f0a.y + e1 * f1a.y + e2 * f2a.y + e3 * f3a.y;
        accS.z += e0 * f0b.x + e1 * f1b.x + e2 * f2b.x + e3 * f3b.x;
        accS.w += e0 * f0b.y + e1 * f1b.y + e2 * f2b.y + e3 * f3b.y;
        accE.x += (ev0.x + ev1.x) + (ev2.x + ev3.x);
        accE.y += (ev0.y + ev1.y) + (ev2.y + ev3.y);
        accE.z += (ev0.z + ev1.z) + (ev2.z + ev3.z);
        accE.w += (ev0.w + ev1.w) + (ev2.w + ev3.w);
    }
    for (; j < end; j++) {
        int2 a = g_edge[j];
        uint2  hv0 = __ldg(&g_hf16[(size_t)a.y * 32 + lane]);
        float4 ev0 = __ldg(&ef4[(size_t)a.x * 32 + lane]);
        float ex0 = 0.f;
        if (lane < 8) {
            float s0 = g_el[a.y * H8 + lane] + er_l;
            s0 = s0 >= 0.f ? s0 : 0.2f * s0;
            ex0 = __expf(s0);
            denom += ex0;
        }
        float e0 = __shfl_sync(0xffffffffu, ex0, lane >> 2);
        float2 f0a = __half22float2(*(__half2*)&hv0.x);
        float2 f0b = __half22float2(*(__half2*)&hv0.y);
        accS.x += e0 * f0a.x;
        accS.y += e0 * f0a.y;
        accS.z += e0 * f0b.x;
        accS.w += e0 * f0b.y;
        accE.x += ev0.x;
        accE.y += ev0.y;
        accE.z += ev0.z;
        accE.w += ev0.w;
    }

    float rd  = (denom > 0.f) ? (1.f / denom) : 0.f;   // valid on lanes 0-7
    float rdh = __shfl_sync(0xffffffffu, rd, lane >> 2);
    accS.x *= rdh; accS.y *= rdh; accS.z *= rdh; accS.w *= rdh;

    ((float4*)g_S)   [(size_t)n * 32 + lane] = accS;
    ((float4*)g_Esum)[(size_t)n * 32 + lane] = accE;
    if (lane == 0) g_indeg[n] = (float)(end - beg);
}

// ---------------- launch ----------------------------------------------------
extern "C" void kernel_launch(void* const* d_in, const int* in_sizes, int n_in,
                              void* d_out, int out_size)
{
    const float* nfeat  = (const float*)d_in[0];
    const float* efeat  = (const float*)d_in[1];
    const int*   src    = (const int*)  d_in[2];
    const int*   dst    = (const int*)  d_in[3];
    const float* W_fc   = (const float*)d_in[4];
    const float* attn_l = (const float*)d_in[5];
    const float* attn_r = (const float*)d_in[6];
    const float* bias   = (const float*)d_in[7];
    const float* W_e    = (const float*)d_in[8];
    const float* b_e    = (const float*)d_in[9];
    float*       out    = (float*)d_out;

    int N = in_sizes[0] / HD;
    int E = in_sizes[2];
    if (N > NMAX) N = NMAX;
    if (E > EMAX) E = EMAX;

    cudaFuncSetAttribute((const void*)gemm128_kernel<0>,
                         cudaFuncAttributeMaxDynamicSharedMemorySize, SM_TOTAL);
    cudaFuncSetAttribute((const void*)gemm128_kernel<1>,
                         cudaFuncAttributeMaxDynamicSharedMemorySize, SM_TOTAL);

    // side stream + fork/join events (created once; reused every call so the
    // captured work is identical on every invocation)
    static cudaStream_t s2 = nullptr;
    static cudaEvent_t  evFork = nullptr, evJoin = nullptr;
    if (s2 == nullptr) {
        cudaStreamCreateWithFlags(&s2, cudaStreamNonBlocking);
        cudaEventCreateWithFlags(&evFork, cudaEventDisableTiming);
        cudaEventCreateWithFlags(&evJoin, cudaEventDisableTiming);
    }

    int nb = (N + 1023) / 1024;

    // ---- fork: CSR build on s2, node GEMM on main stream (independent) ----
    cudaEventRecord(evFork, 0);
    cudaStreamWaitEvent(s2, evFork, 0);

    zero_cnt_kernel<<<(N + 255) / 256, 256, 0, s2>>>(N);
    hist_kernel<<<(E + 255) / 256, 256, 0, s2>>>(dst, E);
    scan1_kernel<<<nb, 1024, 0, s2>>>(N);
    scan3_kernel<<<(N + 255) / 256, 256, 0, s2>>>(nb, E, N);
    scatter_eid_kernel<<<(E + 255) / 256, 256, 0, s2>>>(src, dst, E);
    cudaEventRecord(evJoin, s2);

    // node GEMM (hf, el, er, fp16 shadow) on main stream, concurrent with CSR
    gemm128_kernel<0><<<(N + 63) / 64, 256, SM_TOTAL>>>(
        nfeat, W_fc, N, attn_l, attn_r, nullptr, nullptr, nullptr);

    // ---- join: gather needs both CSR and GEMM0 ----
    cudaStreamWaitEvent(0, evJoin, 0);

    // fused softmax + aggregation + edge-feature sum
    gather_kernel<<<(N * 32 + 255) / 256, 256>>>(efeat, N);

    // edge GEMM (reordered through segment-sum) + final combine
    gemm128_kernel<1><<<(N + 63) / 64, 256, SM_TOTAL>>>(
        nullptr, W_e, N, nullptr, nullptr, bias, b_e, out);
}